// round 1
// baseline (speedup 1.0000x reference)
#include <cuda_runtime.h>
#include <cstdint>

// Problem constants
#define D_MODEL   1024
#define NUM_HEADS 16
#define DEPTH     64
#define BATCH     4
#define SEQ       2048
#define M_TOTAL   (BATCH * SEQ)   // 8192

// ---------------------------------------------------------------------------
// Scratch (allocation-free rule: __device__ globals)
// q/k/v/heads layout: [B][H][S][DEPTH] fp32
// ---------------------------------------------------------------------------
__device__ float g_q[BATCH * NUM_HEADS * SEQ * DEPTH];
__device__ float g_k[BATCH * NUM_HEADS * SEQ * DEPTH];
__device__ float g_v[BATCH * NUM_HEADS * SEQ * DEPTH];
__device__ float g_heads[BATCH * NUM_HEADS * SEQ * DEPTH];

// ---------------------------------------------------------------------------
// TF32 helpers
// ---------------------------------------------------------------------------
__device__ __forceinline__ uint32_t f2tf(float x) {
    uint32_t u;
    asm("cvt.rna.tf32.f32 %0, %1;" : "=r"(u) : "f"(x));
    return u;
}
__device__ __forceinline__ float tfbits(float x) { return __uint_as_float(f2tf(x)); }

// mma.sync m16n8k8 tf32, D += A*B (C aliased to D)
__device__ __forceinline__ void mma8(float d[4], const uint32_t a[4], const uint32_t b[2]) {
    asm volatile(
        "mma.sync.aligned.m16n8k8.row.col.f32.tf32.tf32.f32 "
        "{%0,%1,%2,%3},{%4,%5,%6,%7},{%8,%9},{%0,%1,%2,%3};"
        : "+f"(d[0]), "+f"(d[1]), "+f"(d[2]), "+f"(d[3])
        : "r"(a[0]), "r"(a[1]), "r"(a[2]), "r"(a[3]), "r"(b[0]), "r"(b[1]));
}

// ===========================================================================
// Kernel 1: fused QKV projection
//   C[8192, 3072] = X[8192,1024] * W[1024,3072]  (W = concat(Wq,Wk,Wv) columns)
//   Output scattered to g_q/g_k/g_v in [B][H][S][DEPTH] layout, bias added.
//   Block tile 128x128, K-tile 32, 8 warps (2x4), warp tile 64x32.
// ===========================================================================
__global__ __launch_bounds__(256) void qkv_gemm(
    const float* __restrict__ x,
    const float* __restrict__ Wq, const float* __restrict__ bq,
    const float* __restrict__ Wk, const float* __restrict__ bk,
    const float* __restrict__ Wv, const float* __restrict__ bv)
{
    __shared__ float As[128][36];   // stride 36 -> 36 % 32 = 4: A-frag LDS conflict-free
    __shared__ float Bs[32][136];   // stride 136 -> 136 % 32 = 8: B-frag LDS conflict-free

    const int nBase = blockIdx.x * 128;   // 0..3071, fully inside one of q/k/v
    const int mBase = blockIdx.y * 128;
    const int proj  = nBase >> 10;        // 0=q, 1=k, 2=v (1024 % 128 == 0)
    const int nLoc  = nBase & 1023;

    const float* W    = (proj == 0) ? Wq : (proj == 1) ? Wk : Wv;
    const float* bias = (proj == 0) ? bq : (proj == 1) ? bk : bv;
    float*       dst  = (proj == 0) ? g_q : (proj == 1) ? g_k : g_v;

    const int tid  = threadIdx.x;
    const int warp = tid >> 5;
    const int lane = tid & 31;
    const int g    = lane >> 2;   // group id (0..7)
    const int t4   = lane & 3;    // thread in group
    const int wRow = (warp >> 2) * 64;   // 0 or 64
    const int wCol = (warp & 3) * 32;    // 0,32,64,96

    float acc[4][4][4];
#pragma unroll
    for (int i = 0; i < 4; i++)
#pragma unroll
        for (int j = 0; j < 4; j++)
#pragma unroll
            for (int r = 0; r < 4; r++) acc[i][j][r] = 0.f;

    for (int kb = 0; kb < D_MODEL; kb += 32) {
        // Load A tile 128x32 (float4, coalesced)
#pragma unroll
        for (int i = 0; i < 4; i++) {
            int idx = tid + i * 256;             // 0..1023 float4 slots
            int row = idx >> 3;
            int c4  = (idx & 7) << 2;
            float4 v = *reinterpret_cast<const float4*>(&x[(mBase + row) * D_MODEL + kb + c4]);
            As[row][c4 + 0] = tfbits(v.x);
            As[row][c4 + 1] = tfbits(v.y);
            As[row][c4 + 2] = tfbits(v.z);
            As[row][c4 + 3] = tfbits(v.w);
        }
        // Load B tile 32x128 from W[h][k][e] (scalar; contiguous in e within heads)
#pragma unroll
        for (int i = 0; i < 16; i++) {
            int idx = tid + i * 256;             // 0..4095
            int r   = idx >> 7;
            int c   = idx & 127;
            int n   = nLoc + c;
            int h   = n >> 6, e = n & 63;
            Bs[r][c] = tfbits(W[(h * D_MODEL + (kb + r)) * DEPTH + e]);
        }
        __syncthreads();

#pragma unroll
        for (int kk = 0; kk < 32; kk += 8) {
            uint32_t a[4][4], b[4][2];
#pragma unroll
            for (int mi = 0; mi < 4; mi++) {
                int r0 = wRow + mi * 16 + g;
                a[mi][0] = __float_as_uint(As[r0][kk + t4]);
                a[mi][1] = __float_as_uint(As[r0 + 8][kk + t4]);
                a[mi][2] = __float_as_uint(As[r0][kk + t4 + 4]);
                a[mi][3] = __float_as_uint(As[r0 + 8][kk + t4 + 4]);
            }
#pragma unroll
            for (int ni = 0; ni < 4; ni++) {
                int c0 = wCol + ni * 8 + g;
                b[ni][0] = __float_as_uint(Bs[kk + t4][c0]);
                b[ni][1] = __float_as_uint(Bs[kk + t4 + 4][c0]);
            }
#pragma unroll
            for (int mi = 0; mi < 4; mi++)
#pragma unroll
                for (int ni = 0; ni < 4; ni++) mma8(acc[mi][ni], a[mi], b[ni]);
        }
        __syncthreads();
    }

    // Epilogue: scatter to [B][H][S][DEPTH] with bias
#pragma unroll
    for (int mi = 0; mi < 4; mi++) {
#pragma unroll
        for (int ni = 0; ni < 4; ni++) {
            int row = wRow + mi * 16 + g;
            int col = wCol + ni * 8 + 2 * t4;
#pragma unroll
            for (int r = 0; r < 4; r++) {
                int rr = row + ((r >= 2) ? 8 : 0);
                int cc = col + (r & 1);
                int m  = mBase + rr;
                int n  = nLoc + cc;
                int h  = n >> 6, e = n & 63;
                int bb = m >> 11, s = m & 2047;
                dst[(((bb * NUM_HEADS + h) * SEQ) + s) * DEPTH + e] =
                    acc[mi][ni][r] + bias[h * DEPTH + e];
            }
        }
    }
}

// ===========================================================================
// Kernel 2: flash attention.
//   One CTA per (b,h, 64-row q block). 128 threads = 4 warps, 16 q-rows/warp.
//   S = Q K^T via tf32 MMA, online softmax in fp32, O += P V via tf32 MMA.
// ===========================================================================
#define QS_STRIDE 68   // 68 % 32 == 4 -> A-frag LDS conflict-free
#define VS_STRIDE 72   // 72 % 32 == 8 -> B-frag LDS conflict-free
#define ATT_SMEM_BYTES ((3 * 64 * QS_STRIDE + 64 * VS_STRIDE) * 4)

__global__ __launch_bounds__(128) void attn_kernel()
{
    extern __shared__ float sm[];
    float (*Qs)[QS_STRIDE] = (float (*)[QS_STRIDE])(sm);
    float (*Ks)[QS_STRIDE] = (float (*)[QS_STRIDE])(sm + 64 * QS_STRIDE);
    float (*Ps)[QS_STRIDE] = (float (*)[QS_STRIDE])(sm + 2 * 64 * QS_STRIDE);
    float (*Vs)[VS_STRIDE] = (float (*)[VS_STRIDE])(sm + 3 * 64 * QS_STRIDE);

    const int bh = blockIdx.y;            // 0..63 = b*16+h
    const int qb = blockIdx.x * 64;       // q row base
    const float* Qg = g_q + (size_t)bh * SEQ * DEPTH;
    const float* Kg = g_k + (size_t)bh * SEQ * DEPTH;
    const float* Vg = g_v + (size_t)bh * SEQ * DEPTH;

    const int tid  = threadIdx.x;
    const int warp = tid >> 5;
    const int lane = tid & 31;
    const int g    = lane >> 2;
    const int t4   = lane & 3;
    const int r0   = warp * 16 + g;       // this thread's base row (and r0+8)

    // Load Q tile 64x64 once
#pragma unroll
    for (int i = 0; i < 8; i++) {
        int idx = tid + i * 128;          // 1024 float4
        int row = idx >> 4;
        int c4  = (idx & 15) << 2;
        float4 v = *reinterpret_cast<const float4*>(&Qg[(qb + row) * DEPTH + c4]);
        Qs[row][c4 + 0] = tfbits(v.x);
        Qs[row][c4 + 1] = tfbits(v.y);
        Qs[row][c4 + 2] = tfbits(v.z);
        Qs[row][c4 + 3] = tfbits(v.w);
    }

    float mr0 = -1e30f, mr1 = -1e30f, lr0 = 0.f, lr1 = 0.f;
    float oacc[8][4];
#pragma unroll
    for (int ni = 0; ni < 8; ni++)
#pragma unroll
        for (int r = 0; r < 4; r++) oacc[ni][r] = 0.f;

    for (int kt = 0; kt < SEQ / 64; kt++) {
        // Load K, V tiles 64x64
#pragma unroll
        for (int i = 0; i < 8; i++) {
            int idx = tid + i * 128;
            int row = idx >> 4;
            int c4  = (idx & 15) << 2;
            float4 kv = *reinterpret_cast<const float4*>(&Kg[(kt * 64 + row) * DEPTH + c4]);
            Ks[row][c4 + 0] = tfbits(kv.x);
            Ks[row][c4 + 1] = tfbits(kv.y);
            Ks[row][c4 + 2] = tfbits(kv.z);
            Ks[row][c4 + 3] = tfbits(kv.w);
            float4 vv = *reinterpret_cast<const float4*>(&Vg[(kt * 64 + row) * DEPTH + c4]);
            Vs[row][c4 + 0] = tfbits(vv.x);
            Vs[row][c4 + 1] = tfbits(vv.y);
            Vs[row][c4 + 2] = tfbits(vv.z);
            Vs[row][c4 + 3] = tfbits(vv.w);
        }
        __syncthreads();

        // S = Q K^T  (16 rows/warp x 64 tokens)
        float sacc[8][4];
#pragma unroll
        for (int ni = 0; ni < 8; ni++)
#pragma unroll
            for (int r = 0; r < 4; r++) sacc[ni][r] = 0.f;

#pragma unroll
        for (int kk = 0; kk < 64; kk += 8) {
            uint32_t a[4];
            a[0] = __float_as_uint(Qs[r0][kk + t4]);
            a[1] = __float_as_uint(Qs[r0 + 8][kk + t4]);
            a[2] = __float_as_uint(Qs[r0][kk + t4 + 4]);
            a[3] = __float_as_uint(Qs[r0 + 8][kk + t4 + 4]);
#pragma unroll
            for (int ni = 0; ni < 8; ni++) {
                uint32_t b[2];
                b[0] = __float_as_uint(Ks[ni * 8 + g][kk + t4]);
                b[1] = __float_as_uint(Ks[ni * 8 + g][kk + t4 + 4]);
                mma8(sacc[ni], a, b);
            }
        }

        // Online softmax update (scale = 1/sqrt(64) = 0.125)
        float lm0 = -1e30f, lm1 = -1e30f;
#pragma unroll
        for (int ni = 0; ni < 8; ni++) {
            sacc[ni][0] *= 0.125f; sacc[ni][1] *= 0.125f;
            sacc[ni][2] *= 0.125f; sacc[ni][3] *= 0.125f;
            lm0 = fmaxf(lm0, fmaxf(sacc[ni][0], sacc[ni][1]));
            lm1 = fmaxf(lm1, fmaxf(sacc[ni][2], sacc[ni][3]));
        }
        lm0 = fmaxf(lm0, __shfl_xor_sync(0xffffffffu, lm0, 1));
        lm0 = fmaxf(lm0, __shfl_xor_sync(0xffffffffu, lm0, 2));
        lm1 = fmaxf(lm1, __shfl_xor_sync(0xffffffffu, lm1, 1));
        lm1 = fmaxf(lm1, __shfl_xor_sync(0xffffffffu, lm1, 2));

        float mn0 = fmaxf(mr0, lm0), mn1 = fmaxf(mr1, lm1);
        float al0 = __expf(mr0 - mn0), al1 = __expf(mr1 - mn1);
        float rs0 = 0.f, rs1 = 0.f;
#pragma unroll
        for (int ni = 0; ni < 8; ni++) {
            float p0 = __expf(sacc[ni][0] - mn0);
            float p1 = __expf(sacc[ni][1] - mn0);
            float p2 = __expf(sacc[ni][2] - mn1);
            float p3 = __expf(sacc[ni][3] - mn1);
            rs0 += p0 + p1;
            rs1 += p2 + p3;
            int c = ni * 8 + 2 * t4;
            Ps[r0][c]         = tfbits(p0);
            Ps[r0][c + 1]     = tfbits(p1);
            Ps[r0 + 8][c]     = tfbits(p2);
            Ps[r0 + 8][c + 1] = tfbits(p3);
        }
        rs0 += __shfl_xor_sync(0xffffffffu, rs0, 1);
        rs0 += __shfl_xor_sync(0xffffffffu, rs0, 2);
        rs1 += __shfl_xor_sync(0xffffffffu, rs1, 1);
        rs1 += __shfl_xor_sync(0xffffffffu, rs1, 2);

        lr0 = lr0 * al0 + rs0;
        lr1 = lr1 * al1 + rs1;
        mr0 = mn0; mr1 = mn1;
#pragma unroll
        for (int ni = 0; ni < 8; ni++) {
            oacc[ni][0] *= al0; oacc[ni][1] *= al0;
            oacc[ni][2] *= al1; oacc[ni][3] *= al1;
        }
        __syncwarp();   // Ps is warp-private: writes above visible to warp reads below

        // O += P V
#pragma unroll
        for (int kk = 0; kk < 64; kk += 8) {
            uint32_t a[4];
            a[0] = __float_as_uint(Ps[r0][kk + t4]);
            a[1] = __float_as_uint(Ps[r0 + 8][kk + t4]);
            a[2] = __float_as_uint(Ps[r0][kk + t4 + 4]);
            a[3] = __float_as_uint(Ps[r0 + 8][kk + t4 + 4]);
#pragma unroll
            for (int ni = 0; ni < 8; ni++) {
                uint32_t b[2];
                b[0] = __float_as_uint(Vs[kk + t4][ni * 8 + g]);
                b[1] = __float_as_uint(Vs[kk + t4 + 4][ni * 8 + g]);
                mma8(oacc[ni], a, b);
            }
        }
        __syncthreads();   // all warps done before next tile overwrites Ks/Vs
    }

    // Epilogue: normalize and store to g_heads [B][H][S][DEPTH]
    float inv0 = 1.f / lr0, inv1 = 1.f / lr1;
    float* Og = g_heads + (size_t)bh * SEQ * DEPTH;
#pragma unroll
    for (int ni = 0; ni < 8; ni++) {
        int c = ni * 8 + 2 * t4;
        Og[(qb + r0) * DEPTH + c]         = oacc[ni][0] * inv0;
        Og[(qb + r0) * DEPTH + c + 1]     = oacc[ni][1] * inv0;
        Og[(qb + r0 + 8) * DEPTH + c]     = oacc[ni][2] * inv1;
        Og[(qb + r0 + 8) * DEPTH + c + 1] = oacc[ni][3] * inv1;
    }
}

// ===========================================================================
// Kernel 3: output projection.
//   out[8192,1024] = A[8192,1024] * Wo[1024,1024] + bo
//   A[m][k] = g_heads[b][k/64][s][k%64]  (head-concat transpose folded in)
// ===========================================================================
__global__ __launch_bounds__(256) void out_gemm(
    const float* __restrict__ Wo, const float* __restrict__ bo,
    float* __restrict__ out)
{
    __shared__ float As[128][36];
    __shared__ float Bs[32][136];

    const int nBase = blockIdx.x * 128;
    const int mBase = blockIdx.y * 128;

    const int tid  = threadIdx.x;
    const int warp = tid >> 5;
    const int lane = tid & 31;
    const int g    = lane >> 2;
    const int t4   = lane & 3;
    const int wRow = (warp >> 2) * 64;
    const int wCol = (warp & 3) * 32;

    float acc[4][4][4];
#pragma unroll
    for (int i = 0; i < 4; i++)
#pragma unroll
        for (int j = 0; j < 4; j++)
#pragma unroll
            for (int r = 0; r < 4; r++) acc[i][j][r] = 0.f;

    for (int kb = 0; kb < D_MODEL; kb += 32) {
        // A tile: head-transposed gather (still float4: 32-k tile fits in one head)
#pragma unroll
        for (int i = 0; i < 4; i++) {
            int idx = tid + i * 256;
            int row = idx >> 3;
            int c4  = (idx & 7) << 2;
            int m   = mBase + row;
            int bb  = m >> 11, s = m & 2047;
            int k0  = kb + c4;
            int h   = k0 >> 6, e = k0 & 63;
            float4 v = *reinterpret_cast<const float4*>(
                &g_heads[(((bb * NUM_HEADS + h) * SEQ) + s) * DEPTH + e]);
            As[row][c4 + 0] = tfbits(v.x);
            As[row][c4 + 1] = tfbits(v.y);
            As[row][c4 + 2] = tfbits(v.z);
            As[row][c4 + 3] = tfbits(v.w);
        }
#pragma unroll
        for (int i = 0; i < 16; i++) {
            int idx = tid + i * 256;
            int r   = idx >> 7;
            int c   = idx & 127;
            Bs[r][c] = tfbits(Wo[(kb + r) * D_MODEL + nBase + c]);
        }
        __syncthreads();

#pragma unroll
        for (int kk = 0; kk < 32; kk += 8) {
            uint32_t a[4][4], b[4][2];
#pragma unroll
            for (int mi = 0; mi < 4; mi++) {
                int r0 = wRow + mi * 16 + g;
                a[mi][0] = __float_as_uint(As[r0][kk + t4]);
                a[mi][1] = __float_as_uint(As[r0 + 8][kk + t4]);
                a[mi][2] = __float_as_uint(As[r0][kk + t4 + 4]);
                a[mi][3] = __float_as_uint(As[r0 + 8][kk + t4 + 4]);
            }
#pragma unroll
            for (int ni = 0; ni < 4; ni++) {
                int c0 = wCol + ni * 8 + g;
                b[ni][0] = __float_as_uint(Bs[kk + t4][c0]);
                b[ni][1] = __float_as_uint(Bs[kk + t4 + 4][c0]);
            }
#pragma unroll
            for (int mi = 0; mi < 4; mi++)
#pragma unroll
                for (int ni = 0; ni < 4; ni++) mma8(acc[mi][ni], a[mi], b[ni]);
        }
        __syncthreads();
    }

#pragma unroll
    for (int mi = 0; mi < 4; mi++) {
#pragma unroll
        for (int ni = 0; ni < 4; ni++) {
            int row = wRow + mi * 16 + g;
            int col = wCol + ni * 8 + 2 * t4;
#pragma unroll
            for (int r = 0; r < 4; r++) {
                int rr = row + ((r >= 2) ? 8 : 0);
                int cc = col + (r & 1);
                int m  = mBase + rr;
                int n  = nBase + cc;
                out[m * D_MODEL + n] = acc[mi][ni][r] + bo[n];
            }
        }
    }
}

// ===========================================================================
// Launch
// ===========================================================================
extern "C" void kernel_launch(void* const* d_in, const int* in_sizes, int n_in,
                              void* d_out, int out_size)
{
    (void)in_sizes; (void)n_in; (void)out_size;
    const float* x  = (const float*)d_in[0];
    const float* Wq = (const float*)d_in[1];
    const float* bq = (const float*)d_in[2];
    const float* Wk = (const float*)d_in[3];
    const float* bk = (const float*)d_in[4];
    const float* Wv = (const float*)d_in[5];
    const float* bv = (const float*)d_in[6];
    const float* Wo = (const float*)d_in[7];
    const float* bo = (const float*)d_in[8];
    float* out = (float*)d_out;

    // 1) QKV projection: grid (3072/128, 8192/128)
    qkv_gemm<<<dim3(24, 64), 256>>>(x, Wq, bq, Wk, bk, Wv, bv);

    // 2) Flash attention: grid (2048/64 q-blocks, B*H)
    cudaFuncSetAttribute(attn_kernel, cudaFuncAttributeMaxDynamicSharedMemorySize,
                         ATT_SMEM_BYTES);
    attn_kernel<<<dim3(SEQ / 64, BATCH * NUM_HEADS), 128, ATT_SMEM_BYTES>>>();

    // 3) Output projection: grid (1024/128, 8192/128)
    out_gemm<<<dim3(8, 64), 256>>>(Wo, bo, out);
}

// round 5
// speedup vs baseline: 1.1477x; 1.1477x over previous
#include <cuda_runtime.h>
#include <cstdint>

// Problem constants
#define D_MODEL   1024
#define NUM_HEADS 16
#define DEPTH     64
#define BATCH     4
#define SEQ       2048
#define M_TOTAL   (BATCH * SEQ)   // 8192

// ---------------------------------------------------------------------------
// Scratch (allocation-free rule: __device__ globals)
// ---------------------------------------------------------------------------
__device__ float g_q[BATCH * NUM_HEADS * SEQ * DEPTH];
__device__ float g_k[BATCH * NUM_HEADS * SEQ * DEPTH];
__device__ float g_v[BATCH * NUM_HEADS * SEQ * DEPTH];
__device__ float g_heads[BATCH * NUM_HEADS * SEQ * DEPTH];

// ---------------------------------------------------------------------------
// TF32 helpers
// ---------------------------------------------------------------------------
__device__ __forceinline__ uint32_t f2tf(float x) {
    uint32_t u;
    asm("cvt.rna.tf32.f32 %0, %1;" : "=r"(u) : "f"(x));
    return u;
}
__device__ __forceinline__ float tfbits(float x) { return __uint_as_float(f2tf(x)); }
__device__ __forceinline__ float4 cvt4(float4 v) {
    float4 t;
    t.x = tfbits(v.x); t.y = tfbits(v.y); t.z = tfbits(v.z); t.w = tfbits(v.w);
    return t;
}

// mma.sync m16n8k8 tf32, D += A*B
__device__ __forceinline__ void mma8(float d[4], const uint32_t a[4], const uint32_t b[2]) {
    asm volatile(
        "mma.sync.aligned.m16n8k8.row.col.f32.tf32.tf32.f32 "
        "{%0,%1,%2,%3},{%4,%5,%6,%7},{%8,%9},{%0,%1,%2,%3};"
        : "+f"(d[0]), "+f"(d[1]), "+f"(d[2]), "+f"(d[3])
        : "r"(a[0]), "r"(a[1]), "r"(a[2]), "r"(a[3]), "r"(b[0]), "r"(b[1]));
}

// GEMM smem geometry (double buffered)
#define GA_STRIDE 36    // 36 % 32 == 4 -> A-frag LDS conflict-free
#define GB_STRIDE 136   // 136 % 32 == 8 -> B-frag LDS conflict-free
#define GEMM_SMEM_BYTES ((2 * 128 * GA_STRIDE + 2 * 32 * GB_STRIDE) * 4)

// ===========================================================================
// Kernel 1: fused QKV projection, double-buffered register-staged pipeline.
//   C[8192,3072] = X[8192,1024] * W[1024,3072]; scatter to g_q/g_k/g_v.
//   Block tile 128x128, K-tile 32, 8 warps (2x4), warp tile 64x32.
// ===========================================================================
__global__ __launch_bounds__(256) void qkv_gemm(
    const float* __restrict__ x,
    const float* __restrict__ Wq, const float* __restrict__ bq,
    const float* __restrict__ Wk, const float* __restrict__ bk,
    const float* __restrict__ Wv, const float* __restrict__ bv)
{
    extern __shared__ float sm[];
    float (*As)[GA_STRIDE] = (float (*)[GA_STRIDE])sm;                         // [2*128]
    float (*Bs)[GB_STRIDE] = (float (*)[GB_STRIDE])(sm + 2 * 128 * GA_STRIDE); // [2*32]

    const int nBase = blockIdx.x * 128;
    const int mBase = blockIdx.y * 128;
    const int proj  = nBase >> 10;        // 0=q,1=k,2=v
    const int nLoc  = nBase & 1023;

    const float* W    = (proj == 0) ? Wq : (proj == 1) ? Wk : Wv;
    const float* bias = (proj == 0) ? bq : (proj == 1) ? bk : bv;
    float*       dst  = (proj == 0) ? g_q : (proj == 1) ? g_k : g_v;

    const int tid  = threadIdx.x;
    const int warp = tid >> 5;
    const int lane = tid & 31;
    const int g    = lane >> 2;
    const int t4   = lane & 3;
    const int wRow = (warp >> 2) * 64;
    const int wCol = (warp & 3) * 32;

    // Per-thread load coordinates
    const int aRow = tid >> 3;            // +32 per i
    const int aC4  = (tid & 7) << 2;
    const int bR   = tid >> 5;            // +8 per i
    const int bC4  = (tid & 31) << 2;
    const int bN   = nLoc + bC4;
    const int bH   = bN >> 6;
    const int bE   = bN & 63;

    float4 ra[4], rb[4];

    auto ldg_tiles = [&](int kb) {
#pragma unroll
        for (int i = 0; i < 4; i++)
            ra[i] = *reinterpret_cast<const float4*>(
                &x[(mBase + aRow + i * 32) * D_MODEL + kb + aC4]);
#pragma unroll
        for (int i = 0; i < 4; i++)
            rb[i] = *reinterpret_cast<const float4*>(
                &W[((size_t)bH * D_MODEL + (kb + bR + i * 8)) * DEPTH + bE]);
    };
    auto sts_tiles = [&](int buf) {
#pragma unroll
        for (int i = 0; i < 4; i++)
            *reinterpret_cast<float4*>(&As[buf * 128 + aRow + i * 32][aC4]) = cvt4(ra[i]);
#pragma unroll
        for (int i = 0; i < 4; i++)
            *reinterpret_cast<float4*>(&Bs[buf * 32 + bR + i * 8][bC4]) = cvt4(rb[i]);
    };

    float acc[4][4][4];
#pragma unroll
    for (int i = 0; i < 4; i++)
#pragma unroll
        for (int j = 0; j < 4; j++)
#pragma unroll
            for (int r = 0; r < 4; r++) acc[i][j][r] = 0.f;

    ldg_tiles(0);
    sts_tiles(0);
    __syncthreads();

    const int NIT = D_MODEL / 32;
    for (int it = 0; it < NIT; ++it) {
        const int cur = it & 1, nxt = cur ^ 1;
        if (it + 1 < NIT) ldg_tiles((it + 1) * 32);

#pragma unroll
        for (int kk = 0; kk < 32; kk += 8) {
            uint32_t a[4][4], b[4][2];
#pragma unroll
            for (int mi = 0; mi < 4; mi++) {
                int r0 = cur * 128 + wRow + mi * 16 + g;
                a[mi][0] = __float_as_uint(As[r0][kk + t4]);
                a[mi][1] = __float_as_uint(As[r0 + 8][kk + t4]);
                a[mi][2] = __float_as_uint(As[r0][kk + t4 + 4]);
                a[mi][3] = __float_as_uint(As[r0 + 8][kk + t4 + 4]);
            }
#pragma unroll
            for (int ni = 0; ni < 4; ni++) {
                int c0 = wCol + ni * 8 + g;
                b[ni][0] = __float_as_uint(Bs[cur * 32 + kk + t4][c0]);
                b[ni][1] = __float_as_uint(Bs[cur * 32 + kk + t4 + 4][c0]);
            }
#pragma unroll
            for (int mi = 0; mi < 4; mi++)
#pragma unroll
                for (int ni = 0; ni < 4; ni++) mma8(acc[mi][ni], a[mi], b[ni]);
        }

        if (it + 1 < NIT) sts_tiles(nxt);
        __syncthreads();
    }

    // Epilogue: scatter to [B][H][S][DEPTH] with bias
#pragma unroll
    for (int mi = 0; mi < 4; mi++) {
#pragma unroll
        for (int ni = 0; ni < 4; ni++) {
            int row = wRow + mi * 16 + g;
            int col = wCol + ni * 8 + 2 * t4;
#pragma unroll
            for (int r = 0; r < 4; r++) {
                int rr = row + ((r >= 2) ? 8 : 0);
                int cc = col + (r & 1);
                int m  = mBase + rr;
                int n  = nLoc + cc;
                int h  = n >> 6, e = n & 63;
                int bb = m >> 11, s = m & 2047;
                dst[(((bb * NUM_HEADS + h) * SEQ) + s) * DEPTH + e] =
                    acc[mi][ni][r] + bias[h * DEPTH + e];
            }
        }
    }
}

// ===========================================================================
// Kernel 2: flash attention, 128-row q-tile, 8 warps (256 thr), double-
//   buffered K/V with register staging. One CTA per (b,h, 128-row q block).
//   Each warp owns 16 q-rows — warp-level math identical to the 64-row
//   version, so numerics are bit-identical.
// ===========================================================================
#define QS 68   // 68 % 32 == 4  -> A-frag LDS conflict-free
#define VS 72   // 72 % 32 == 8  -> B-frag LDS conflict-free
#define QROWS 128
#define ATT_SMEM_BYTES ((QROWS * QS /*Qs*/ + QROWS * QS /*Ps*/ \
                         + 2 * 64 * QS /*Ks*/ + 2 * 64 * VS /*Vs*/) * 4)

__global__ __launch_bounds__(256) void attn_kernel()
{
    extern __shared__ float sm[];
    float (*Qs)[QS] = (float (*)[QS])sm;                          // [128]
    float (*Ps)[QS] = (float (*)[QS])(sm + QROWS * QS);           // [128]
    float (*Ks)[QS] = (float (*)[QS])(sm + 2 * QROWS * QS);       // [2*64]
    float (*Vs)[VS] = (float (*)[VS])(sm + 2 * QROWS * QS + 2 * 64 * QS); // [2*64]

    const int bh = blockIdx.y;
    const int qb = blockIdx.x * QROWS;
    const float* Qg = g_q + (size_t)bh * SEQ * DEPTH;
    const float* Kg = g_k + (size_t)bh * SEQ * DEPTH;
    const float* Vg = g_v + (size_t)bh * SEQ * DEPTH;

    const int tid  = threadIdx.x;
    const int warp = tid >> 5;            // 0..7
    const int lane = tid & 31;
    const int g    = lane >> 2;
    const int t4   = lane & 3;
    const int r0   = warp * 16 + g;       // 0..119 (+8 -> up to 127)

    const int lRow = tid >> 4;            // 0..15
    const int lC4  = (tid & 15) << 2;

    // Load Q 128x64 (pre-scaled by 1/sqrt(64); exact pow2, rounding-neutral)
#pragma unroll
    for (int i = 0; i < 8; i++) {
        int row = lRow + i * 16;          // 0..127
        float4 v = *reinterpret_cast<const float4*>(&Qg[(qb + row) * DEPTH + lC4]);
        v.x *= 0.125f; v.y *= 0.125f; v.z *= 0.125f; v.w *= 0.125f;
        *reinterpret_cast<float4*>(&Qs[row][lC4]) = cvt4(v);
    }
    // Load K0, V0 (64 rows each)
#pragma unroll
    for (int i = 0; i < 4; i++) {
        int row = lRow + i * 16;          // 0..63
        float4 kv = *reinterpret_cast<const float4*>(&Kg[row * DEPTH + lC4]);
        *reinterpret_cast<float4*>(&Ks[row][lC4]) = cvt4(kv);
        float4 vv = *reinterpret_cast<const float4*>(&Vg[row * DEPTH + lC4]);
        *reinterpret_cast<float4*>(&Vs[row][lC4]) = cvt4(vv);
    }
    __syncthreads();

    float mr0 = -1e30f, mr1 = -1e30f, lr0 = 0.f, lr1 = 0.f;
    float oacc[8][4];
#pragma unroll
    for (int ni = 0; ni < 8; ni++)
#pragma unroll
        for (int r = 0; r < 4; r++) oacc[ni][r] = 0.f;

    const int NT = SEQ / 64;
    for (int kt = 0; kt < NT; kt++) {
        const int cur = kt & 1, nxt = cur ^ 1;
        const bool pf = (kt + 1 < NT);

        // Prefetch next K into registers (hidden under S-MMA)
        float4 rk[4];
        if (pf) {
            const float* Kn = Kg + (size_t)(kt + 1) * 64 * DEPTH;
#pragma unroll
            for (int i = 0; i < 4; i++)
                rk[i] = *reinterpret_cast<const float4*>(&Kn[(lRow + i * 16) * DEPTH + lC4]);
        }

        // S = Q K^T  (16 rows/warp x 64 tokens)
        float sacc[8][4];
#pragma unroll
        for (int ni = 0; ni < 8; ni++)
#pragma unroll
            for (int r = 0; r < 4; r++) sacc[ni][r] = 0.f;

#pragma unroll
        for (int kk = 0; kk < 64; kk += 8) {
            uint32_t a[4];
            a[0] = __float_as_uint(Qs[r0][kk + t4]);
            a[1] = __float_as_uint(Qs[r0 + 8][kk + t4]);
            a[2] = __float_as_uint(Qs[r0][kk + t4 + 4]);
            a[3] = __float_as_uint(Qs[r0 + 8][kk + t4 + 4]);
#pragma unroll
            for (int ni = 0; ni < 8; ni++) {
                uint32_t b[2];
                b[0] = __float_as_uint(Ks[cur * 64 + ni * 8 + g][kk + t4]);
                b[1] = __float_as_uint(Ks[cur * 64 + ni * 8 + g][kk + t4 + 4]);
                mma8(sacc[ni], a, b);
            }
        }

        // Online softmax (Q already scaled)
        float lm0 = -1e30f, lm1 = -1e30f;
#pragma unroll
        for (int ni = 0; ni < 8; ni++) {
            lm0 = fmaxf(lm0, fmaxf(sacc[ni][0], sacc[ni][1]));
            lm1 = fmaxf(lm1, fmaxf(sacc[ni][2], sacc[ni][3]));
        }
        lm0 = fmaxf(lm0, __shfl_xor_sync(0xffffffffu, lm0, 1));
        lm0 = fmaxf(lm0, __shfl_xor_sync(0xffffffffu, lm0, 2));
        lm1 = fmaxf(lm1, __shfl_xor_sync(0xffffffffu, lm1, 1));
        lm1 = fmaxf(lm1, __shfl_xor_sync(0xffffffffu, lm1, 2));

        float mn0 = fmaxf(mr0, lm0), mn1 = fmaxf(mr1, lm1);
        float al0 = __expf(mr0 - mn0), al1 = __expf(mr1 - mn1);
        float rs0 = 0.f, rs1 = 0.f;
#pragma unroll
        for (int ni = 0; ni < 8; ni++) {
            float p0 = __expf(sacc[ni][0] - mn0);
            float p1 = __expf(sacc[ni][1] - mn0);
            float p2 = __expf(sacc[ni][2] - mn1);
            float p3 = __expf(sacc[ni][3] - mn1);
            rs0 += p0 + p1;
            rs1 += p2 + p3;
            int c = ni * 8 + 2 * t4;
            Ps[r0][c]         = tfbits(p0);
            Ps[r0][c + 1]     = tfbits(p1);
            Ps[r0 + 8][c]     = tfbits(p2);
            Ps[r0 + 8][c + 1] = tfbits(p3);
        }
        rs0 += __shfl_xor_sync(0xffffffffu, rs0, 1);
        rs0 += __shfl_xor_sync(0xffffffffu, rs0, 2);
        rs1 += __shfl_xor_sync(0xffffffffu, rs1, 1);
        rs1 += __shfl_xor_sync(0xffffffffu, rs1, 2);

        lr0 = lr0 * al0 + rs0;
        lr1 = lr1 * al1 + rs1;
        mr0 = mn0; mr1 = mn1;
#pragma unroll
        for (int ni = 0; ni < 8; ni++) {
            oacc[ni][0] *= al0; oacc[ni][1] *= al0;
            oacc[ni][2] *= al1; oacc[ni][3] *= al1;
        }

        // Drain K staging regs into next buffer (rk dead before rv loads)
        if (pf) {
#pragma unroll
            for (int i = 0; i < 4; i++)
                *reinterpret_cast<float4*>(&Ks[nxt * 64 + lRow + i * 16][lC4]) = cvt4(rk[i]);
        }
        // Prefetch next V (hidden under PV-MMA)
        float4 rv[4];
        if (pf) {
            const float* Vn = Vg + (size_t)(kt + 1) * 64 * DEPTH;
#pragma unroll
            for (int i = 0; i < 4; i++)
                rv[i] = *reinterpret_cast<const float4*>(&Vn[(lRow + i * 16) * DEPTH + lC4]);
        }
        __syncwarp();   // Ps rows warp-private: writes above visible to this warp's reads

        // O += P V
#pragma unroll
        for (int kk = 0; kk < 64; kk += 8) {
            uint32_t a[4];
            a[0] = __float_as_uint(Ps[r0][kk + t4]);
            a[1] = __float_as_uint(Ps[r0 + 8][kk + t4]);
            a[2] = __float_as_uint(Ps[r0][kk + t4 + 4]);
            a[3] = __float_as_uint(Ps[r0 + 8][kk + t4 + 4]);
#pragma unroll
            for (int ni = 0; ni < 8; ni++) {
                uint32_t b[2];
                b[0] = __float_as_uint(Vs[cur * 64 + kk + t4][ni * 8 + g]);
                b[1] = __float_as_uint(Vs[cur * 64 + kk + t4 + 4][ni * 8 + g]);
                mma8(oacc[ni], a, b);
            }
        }

        if (pf) {
#pragma unroll
            for (int i = 0; i < 4; i++)
                *reinterpret_cast<float4*>(&Vs[nxt * 64 + lRow + i * 16][lC4]) = cvt4(rv[i]);
        }
        __syncthreads();
    }

    // Epilogue
    float inv0 = 1.f / lr0, inv1 = 1.f / lr1;
    float* Og = g_heads + (size_t)bh * SEQ * DEPTH;
#pragma unroll
    for (int ni = 0; ni < 8; ni++) {
        int c = ni * 8 + 2 * t4;
        Og[(qb + r0) * DEPTH + c]         = oacc[ni][0] * inv0;
        Og[(qb + r0) * DEPTH + c + 1]     = oacc[ni][1] * inv0;
        Og[(qb + r0 + 8) * DEPTH + c]     = oacc[ni][2] * inv1;
        Og[(qb + r0 + 8) * DEPTH + c + 1] = oacc[ni][3] * inv1;
    }
}

// ===========================================================================
// Kernel 3: output projection, same pipelined structure.
//   out[8192,1024] = heads_concat[8192,1024] * Wo[1024,1024] + bo
//   A[m][k] = g_heads[b][k/64][s][k%64]  (head-concat transpose folded in)
// ===========================================================================
__global__ __launch_bounds__(256) void out_gemm(
    const float* __restrict__ Wo, const float* __restrict__ bo,
    float* __restrict__ out)
{
    extern __shared__ float sm[];
    float (*As)[GA_STRIDE] = (float (*)[GA_STRIDE])sm;
    float (*Bs)[GB_STRIDE] = (float (*)[GB_STRIDE])(sm + 2 * 128 * GA_STRIDE);

    const int nBase = blockIdx.x * 128;
    const int mBase = blockIdx.y * 128;

    const int tid  = threadIdx.x;
    const int warp = tid >> 5;
    const int lane = tid & 31;
    const int g    = lane >> 2;
    const int t4   = lane & 3;
    const int wRow = (warp >> 2) * 64;
    const int wCol = (warp & 3) * 32;

    const int aRow = tid >> 3;
    const int aC4  = (tid & 7) << 2;
    const int bR   = tid >> 5;
    const int bC4  = (tid & 31) << 2;

    float4 ra[4], rb[4];

    auto ldg_tiles = [&](int kb) {
        const int h = kb >> 6, e0 = (kb & 63) + aC4;   // kb 32-aligned: tile stays in one head
#pragma unroll
        for (int i = 0; i < 4; i++) {
            int m  = mBase + aRow + i * 32;
            int bb = m >> 11, s = m & 2047;
            ra[i] = *reinterpret_cast<const float4*>(
                &g_heads[(((size_t)(bb * NUM_HEADS + h) * SEQ) + s) * DEPTH + e0]);
        }
#pragma unroll
        for (int i = 0; i < 4; i++)
            rb[i] = *reinterpret_cast<const float4*>(
                &Wo[(size_t)(kb + bR + i * 8) * D_MODEL + nBase + bC4]);
    };
    auto sts_tiles = [&](int buf) {
#pragma unroll
        for (int i = 0; i < 4; i++)
            *reinterpret_cast<float4*>(&As[buf * 128 + aRow + i * 32][aC4]) = cvt4(ra[i]);
#pragma unroll
        for (int i = 0; i < 4; i++)
            *reinterpret_cast<float4*>(&Bs[buf * 32 + bR + i * 8][bC4]) = cvt4(rb[i]);
    };

    float acc[4][4][4];
#pragma unroll
    for (int i = 0; i < 4; i++)
#pragma unroll
        for (int j = 0; j < 4; j++)
#pragma unroll
            for (int r = 0; r < 4; r++) acc[i][j][r] = 0.f;

    ldg_tiles(0);
    sts_tiles(0);
    __syncthreads();

    const int NIT = D_MODEL / 32;
    for (int it = 0; it < NIT; ++it) {
        const int cur = it & 1, nxt = cur ^ 1;
        if (it + 1 < NIT) ldg_tiles((it + 1) * 32);

#pragma unroll
        for (int kk = 0; kk < 32; kk += 8) {
            uint32_t a[4][4], b[4][2];
#pragma unroll
            for (int mi = 0; mi < 4; mi++) {
                int r0 = cur * 128 + wRow + mi * 16 + g;
                a[mi][0] = __float_as_uint(As[r0][kk + t4]);
                a[mi][1] = __float_as_uint(As[r0 + 8][kk + t4]);
                a[mi][2] = __float_as_uint(As[r0][kk + t4 + 4]);
                a[mi][3] = __float_as_uint(As[r0 + 8][kk + t4 + 4]);
            }
#pragma unroll
            for (int ni = 0; ni < 4; ni++) {
                int c0 = wCol + ni * 8 + g;
                b[ni][0] = __float_as_uint(Bs[cur * 32 + kk + t4][c0]);
                b[ni][1] = __float_as_uint(Bs[cur * 32 + kk + t4 + 4][c0]);
            }
#pragma unroll
            for (int mi = 0; mi < 4; mi++)
#pragma unroll
                for (int ni = 0; ni < 4; ni++) mma8(acc[mi][ni], a[mi], b[ni]);
        }

        if (it + 1 < NIT) sts_tiles(nxt);
        __syncthreads();
    }

#pragma unroll
    for (int mi = 0; mi < 4; mi++) {
#pragma unroll
        for (int ni = 0; ni < 4; ni++) {
            int row = wRow + mi * 16 + g;
            int col = wCol + ni * 8 + 2 * t4;
#pragma unroll
            for (int r = 0; r < 4; r++) {
                int rr = row + ((r >= 2) ? 8 : 0);
                int cc = col + (r & 1);
                int m  = mBase + rr;
                int n  = nBase + cc;
                out[m * D_MODEL + n] = acc[mi][ni][r] + bo[n];
            }
        }
    }
}

// ===========================================================================
// Launch
// ===========================================================================
extern "C" void kernel_launch(void* const* d_in, const int* in_sizes, int n_in,
                              void* d_out, int out_size)
{
    (void)in_sizes; (void)n_in; (void)out_size;
    const float* x  = (const float*)d_in[0];
    const float* Wq = (const float*)d_in[1];
    const float* bq = (const float*)d_in[2];
    const float* Wk = (const float*)d_in[3];
    const float* bk = (const float*)d_in[4];
    const float* Wv = (const float*)d_in[5];
    const float* bv = (const float*)d_in[6];
    const float* Wo = (const float*)d_in[7];
    const float* bo = (const float*)d_in[8];
    float* out = (float*)d_out;

    // No static guards (harness rule): set attributes unconditionally.
    cudaFuncSetAttribute(qkv_gemm, cudaFuncAttributeMaxDynamicSharedMemorySize,
                         GEMM_SMEM_BYTES);
    cudaFuncSetAttribute(out_gemm, cudaFuncAttributeMaxDynamicSharedMemorySize,
                         GEMM_SMEM_BYTES);
    cudaFuncSetAttribute(attn_kernel, cudaFuncAttributeMaxDynamicSharedMemorySize,
                         ATT_SMEM_BYTES);

    qkv_gemm<<<dim3(24, 64), 256, GEMM_SMEM_BYTES>>>(x, Wq, bq, Wk, bk, Wv, bv);
    attn_kernel<<<dim3(SEQ / QROWS, BATCH * NUM_HEADS), 256, ATT_SMEM_BYTES>>>();
    out_gemm<<<dim3(8, 64), 256, GEMM_SMEM_BYTES>>>(Wo, bo, out);
}

// round 6
// speedup vs baseline: 1.3120x; 1.1432x over previous
#include <cuda_runtime.h>
#include <cstdint>

// Problem constants
#define D_MODEL   1024
#define NUM_HEADS 16
#define DEPTH     64
#define BATCH     4
#define SEQ       2048
#define M_TOTAL   (BATCH * SEQ)   // 8192

// ---------------------------------------------------------------------------
// Scratch (allocation-free rule: __device__ globals)
// ---------------------------------------------------------------------------
__device__ float g_q[BATCH * NUM_HEADS * SEQ * DEPTH];
__device__ float g_k[BATCH * NUM_HEADS * SEQ * DEPTH];
__device__ float g_v[BATCH * NUM_HEADS * SEQ * DEPTH];
__device__ float g_heads[BATCH * NUM_HEADS * SEQ * DEPTH];

// ---------------------------------------------------------------------------
// TF32 helpers
// ---------------------------------------------------------------------------
__device__ __forceinline__ uint32_t f2tf(float x) {
    uint32_t u;
    asm("cvt.rna.tf32.f32 %0, %1;" : "=r"(u) : "f"(x));
    return u;
}
__device__ __forceinline__ float tfbits(float x) { return __uint_as_float(f2tf(x)); }
__device__ __forceinline__ float4 cvt4(float4 v) {
    float4 t;
    t.x = tfbits(v.x); t.y = tfbits(v.y); t.z = tfbits(v.z); t.w = tfbits(v.w);
    return t;
}

// mma.sync m16n8k8 tf32, D += A*B
__device__ __forceinline__ void mma8(float d[4], const uint32_t a[4], const uint32_t b[2]) {
    asm volatile(
        "mma.sync.aligned.m16n8k8.row.col.f32.tf32.tf32.f32 "
        "{%0,%1,%2,%3},{%4,%5,%6,%7},{%8,%9},{%0,%1,%2,%3};"
        : "+f"(d[0]), "+f"(d[1]), "+f"(d[2]), "+f"(d[3])
        : "r"(a[0]), "r"(a[1]), "r"(a[2]), "r"(a[3]), "r"(b[0]), "r"(b[1]));
}

// GEMM smem geometry (double buffered)
#define GA_STRIDE 36    // 36 % 32 == 4 -> A-frag LDS conflict-free
#define GB_STRIDE 136   // 136 % 32 == 8 -> B-frag LDS conflict-free
#define GEMM_SMEM_BYTES ((2 * 128 * GA_STRIDE + 2 * 32 * GB_STRIDE) * 4)

// ===========================================================================
// Kernel 1: fused QKV projection (UNCHANGED from R5 — measured control).
// ===========================================================================
__global__ __launch_bounds__(256) void qkv_gemm(
    const float* __restrict__ x,
    const float* __restrict__ Wq, const float* __restrict__ bq,
    const float* __restrict__ Wk, const float* __restrict__ bk,
    const float* __restrict__ Wv, const float* __restrict__ bv)
{
    extern __shared__ float sm[];
    float (*As)[GA_STRIDE] = (float (*)[GA_STRIDE])sm;                         // [2*128]
    float (*Bs)[GB_STRIDE] = (float (*)[GB_STRIDE])(sm + 2 * 128 * GA_STRIDE); // [2*32]

    const int nBase = blockIdx.x * 128;
    const int mBase = blockIdx.y * 128;
    const int proj  = nBase >> 10;        // 0=q,1=k,2=v
    const int nLoc  = nBase & 1023;

    const float* W    = (proj == 0) ? Wq : (proj == 1) ? Wk : Wv;
    const float* bias = (proj == 0) ? bq : (proj == 1) ? bk : bv;
    float*       dst  = (proj == 0) ? g_q : (proj == 1) ? g_k : g_v;

    const int tid  = threadIdx.x;
    const int warp = tid >> 5;
    const int lane = tid & 31;
    const int g    = lane >> 2;
    const int t4   = lane & 3;
    const int wRow = (warp >> 2) * 64;
    const int wCol = (warp & 3) * 32;

    const int aRow = tid >> 3;
    const int aC4  = (tid & 7) << 2;
    const int bR   = tid >> 5;
    const int bC4  = (tid & 31) << 2;
    const int bN   = nLoc + bC4;
    const int bH   = bN >> 6;
    const int bE   = bN & 63;

    float4 ra[4], rb[4];

    auto ldg_tiles = [&](int kb) {
#pragma unroll
        for (int i = 0; i < 4; i++)
            ra[i] = *reinterpret_cast<const float4*>(
                &x[(mBase + aRow + i * 32) * D_MODEL + kb + aC4]);
#pragma unroll
        for (int i = 0; i < 4; i++)
            rb[i] = *reinterpret_cast<const float4*>(
                &W[((size_t)bH * D_MODEL + (kb + bR + i * 8)) * DEPTH + bE]);
    };
    auto sts_tiles = [&](int buf) {
#pragma unroll
        for (int i = 0; i < 4; i++)
            *reinterpret_cast<float4*>(&As[buf * 128 + aRow + i * 32][aC4]) = cvt4(ra[i]);
#pragma unroll
        for (int i = 0; i < 4; i++)
            *reinterpret_cast<float4*>(&Bs[buf * 32 + bR + i * 8][bC4]) = cvt4(rb[i]);
    };

    float acc[4][4][4];
#pragma unroll
    for (int i = 0; i < 4; i++)
#pragma unroll
        for (int j = 0; j < 4; j++)
#pragma unroll
            for (int r = 0; r < 4; r++) acc[i][j][r] = 0.f;

    ldg_tiles(0);
    sts_tiles(0);
    __syncthreads();

    const int NIT = D_MODEL / 32;
    for (int it = 0; it < NIT; ++it) {
        const int cur = it & 1, nxt = cur ^ 1;
        if (it + 1 < NIT) ldg_tiles((it + 1) * 32);

#pragma unroll
        for (int kk = 0; kk < 32; kk += 8) {
            uint32_t a[4][4], b[4][2];
#pragma unroll
            for (int mi = 0; mi < 4; mi++) {
                int r0 = cur * 128 + wRow + mi * 16 + g;
                a[mi][0] = __float_as_uint(As[r0][kk + t4]);
                a[mi][1] = __float_as_uint(As[r0 + 8][kk + t4]);
                a[mi][2] = __float_as_uint(As[r0][kk + t4 + 4]);
                a[mi][3] = __float_as_uint(As[r0 + 8][kk + t4 + 4]);
            }
#pragma unroll
            for (int ni = 0; ni < 4; ni++) {
                int c0 = wCol + ni * 8 + g;
                b[ni][0] = __float_as_uint(Bs[cur * 32 + kk + t4][c0]);
                b[ni][1] = __float_as_uint(Bs[cur * 32 + kk + t4 + 4][c0]);
            }
#pragma unroll
            for (int mi = 0; mi < 4; mi++)
#pragma unroll
                for (int ni = 0; ni < 4; ni++) mma8(acc[mi][ni], a[mi], b[ni]);
        }

        if (it + 1 < NIT) sts_tiles(nxt);
        __syncthreads();
    }

#pragma unroll
    for (int mi = 0; mi < 4; mi++) {
#pragma unroll
        for (int ni = 0; ni < 4; ni++) {
            int row = wRow + mi * 16 + g;
            int col = wCol + ni * 8 + 2 * t4;
#pragma unroll
            for (int r = 0; r < 4; r++) {
                int rr = row + ((r >= 2) ? 8 : 0);
                int cc = col + (r & 1);
                int m  = mBase + rr;
                int n  = nLoc + cc;
                int h  = n >> 6, e = n & 63;
                int bb = m >> 11, s = m & 2047;
                dst[(((bb * NUM_HEADS + h) * SEQ) + s) * DEPTH + e] =
                    acc[mi][ni][r] + bias[h * DEPTH + e];
            }
        }
    }
}

// ===========================================================================
// Kernel 2: flash attention v3 — occupancy over pipelining.
//   128-row q-tile, 8 warps, SINGLE-buffered K/V, Q+P in smem.
//   smem = 105,472 B -> 2 CTAs/SM = 4 warps/SMSP: the co-resident CTA hides
//   both the per-tile K/V load phase and the serial softmax chains.
// ===========================================================================
#define QS 68   // 68 % 32 == 4  -> A-frag LDS conflict-free
#define VS 72   // 72 % 32 == 8  -> B-frag LDS conflict-free
#define QROWS 128
#define ATT_SMEM_BYTES ((2 * QROWS * QS /*Qs+Ps*/ + 64 * QS /*Ks*/ + 64 * VS /*Vs*/) * 4)

__global__ __launch_bounds__(256, 2) void attn_kernel()
{
    extern __shared__ float sm[];
    float (*Qs)[QS] = (float (*)[QS])sm;                             // [128]
    float (*Ps)[QS] = (float (*)[QS])(sm + QROWS * QS);              // [128]
    float (*Ks)[QS] = (float (*)[QS])(sm + 2 * QROWS * QS);          // [64]
    float (*Vs)[VS] = (float (*)[VS])(sm + 2 * QROWS * QS + 64 * QS);// [64]

    const int bh = blockIdx.y;
    const int qb = blockIdx.x * QROWS;
    const float* Qg = g_q + (size_t)bh * SEQ * DEPTH;
    const float* Kg = g_k + (size_t)bh * SEQ * DEPTH;
    const float* Vg = g_v + (size_t)bh * SEQ * DEPTH;

    const int tid  = threadIdx.x;
    const int warp = tid >> 5;            // 0..7
    const int lane = tid & 31;
    const int g    = lane >> 2;
    const int t4   = lane & 3;
    const int r0   = warp * 16 + g;       // 0..119 (+8 -> 127)

    const int lRow = tid >> 4;            // 0..15
    const int lC4  = (tid & 15) << 2;

    // Load Q 128x64 once (pre-scaled by 1/sqrt(64); exact pow2)
#pragma unroll
    for (int i = 0; i < 8; i++) {
        int row = lRow + i * 16;          // 0..127
        float4 v = *reinterpret_cast<const float4*>(&Qg[(qb + row) * DEPTH + lC4]);
        v.x *= 0.125f; v.y *= 0.125f; v.z *= 0.125f; v.w *= 0.125f;
        *reinterpret_cast<float4*>(&Qs[row][lC4]) = cvt4(v);
    }

    float mr0 = -1e30f, mr1 = -1e30f, lr0 = 0.f, lr1 = 0.f;
    float oacc[8][4];
#pragma unroll
    for (int ni = 0; ni < 8; ni++)
#pragma unroll
        for (int r = 0; r < 4; r++) oacc[ni][r] = 0.f;

    const int NT = SEQ / 64;
    for (int kt = 0; kt < NT; kt++) {
        // Load K, V tile (single buffer; other CTA on the SM hides this)
#pragma unroll
        for (int i = 0; i < 4; i++) {
            int row = lRow + i * 16;      // 0..63
            float4 kv = *reinterpret_cast<const float4*>(
                &Kg[((size_t)kt * 64 + row) * DEPTH + lC4]);
            *reinterpret_cast<float4*>(&Ks[row][lC4]) = cvt4(kv);
            float4 vv = *reinterpret_cast<const float4*>(
                &Vg[((size_t)kt * 64 + row) * DEPTH + lC4]);
            *reinterpret_cast<float4*>(&Vs[row][lC4]) = cvt4(vv);
        }
        __syncthreads();

        // S = Q K^T  (16 rows/warp x 64 tokens)
        float sacc[8][4];
#pragma unroll
        for (int ni = 0; ni < 8; ni++)
#pragma unroll
            for (int r = 0; r < 4; r++) sacc[ni][r] = 0.f;

#pragma unroll
        for (int kk = 0; kk < 64; kk += 8) {
            uint32_t a[4];
            a[0] = __float_as_uint(Qs[r0][kk + t4]);
            a[1] = __float_as_uint(Qs[r0 + 8][kk + t4]);
            a[2] = __float_as_uint(Qs[r0][kk + t4 + 4]);
            a[3] = __float_as_uint(Qs[r0 + 8][kk + t4 + 4]);
#pragma unroll
            for (int ni = 0; ni < 8; ni++) {
                uint32_t b[2];
                b[0] = __float_as_uint(Ks[ni * 8 + g][kk + t4]);
                b[1] = __float_as_uint(Ks[ni * 8 + g][kk + t4 + 4]);
                mma8(sacc[ni], a, b);
            }
        }

        // Online softmax (Q already scaled)
        float lm0 = -1e30f, lm1 = -1e30f;
#pragma unroll
        for (int ni = 0; ni < 8; ni++) {
            lm0 = fmaxf(lm0, fmaxf(sacc[ni][0], sacc[ni][1]));
            lm1 = fmaxf(lm1, fmaxf(sacc[ni][2], sacc[ni][3]));
        }
        lm0 = fmaxf(lm0, __shfl_xor_sync(0xffffffffu, lm0, 1));
        lm0 = fmaxf(lm0, __shfl_xor_sync(0xffffffffu, lm0, 2));
        lm1 = fmaxf(lm1, __shfl_xor_sync(0xffffffffu, lm1, 1));
        lm1 = fmaxf(lm1, __shfl_xor_sync(0xffffffffu, lm1, 2));

        float mn0 = fmaxf(mr0, lm0), mn1 = fmaxf(mr1, lm1);
        float al0 = __expf(mr0 - mn0), al1 = __expf(mr1 - mn1);
        float rs0 = 0.f, rs1 = 0.f;
#pragma unroll
        for (int ni = 0; ni < 8; ni++) {
            float p0 = __expf(sacc[ni][0] - mn0);
            float p1 = __expf(sacc[ni][1] - mn0);
            float p2 = __expf(sacc[ni][2] - mn1);
            float p3 = __expf(sacc[ni][3] - mn1);
            rs0 += p0 + p1;
            rs1 += p2 + p3;
            int c = ni * 8 + 2 * t4;
            Ps[r0][c]         = tfbits(p0);
            Ps[r0][c + 1]     = tfbits(p1);
            Ps[r0 + 8][c]     = tfbits(p2);
            Ps[r0 + 8][c + 1] = tfbits(p3);
        }
        rs0 += __shfl_xor_sync(0xffffffffu, rs0, 1);
        rs0 += __shfl_xor_sync(0xffffffffu, rs0, 2);
        rs1 += __shfl_xor_sync(0xffffffffu, rs1, 1);
        rs1 += __shfl_xor_sync(0xffffffffu, rs1, 2);

        lr0 = lr0 * al0 + rs0;
        lr1 = lr1 * al1 + rs1;
        mr0 = mn0; mr1 = mn1;
#pragma unroll
        for (int ni = 0; ni < 8; ni++) {
            oacc[ni][0] *= al0; oacc[ni][1] *= al0;
            oacc[ni][2] *= al1; oacc[ni][3] *= al1;
        }
        __syncwarp();   // Ps rows warp-private: writes visible to this warp's reads

        // O += P V
#pragma unroll
        for (int kk = 0; kk < 64; kk += 8) {
            uint32_t a[4];
            a[0] = __float_as_uint(Ps[r0][kk + t4]);
            a[1] = __float_as_uint(Ps[r0 + 8][kk + t4]);
            a[2] = __float_as_uint(Ps[r0][kk + t4 + 4]);
            a[3] = __float_as_uint(Ps[r0 + 8][kk + t4 + 4]);
#pragma unroll
            for (int ni = 0; ni < 8; ni++) {
                uint32_t b[2];
                b[0] = __float_as_uint(Vs[kk + t4][ni * 8 + g]);
                b[1] = __float_as_uint(Vs[kk + t4 + 4][ni * 8 + g]);
                mma8(oacc[ni], a, b);
            }
        }
        __syncthreads();   // all warps done with Ks/Vs before next tile's stores
    }

    // Epilogue
    float inv0 = 1.f / lr0, inv1 = 1.f / lr1;
    float* Og = g_heads + (size_t)bh * SEQ * DEPTH;
#pragma unroll
    for (int ni = 0; ni < 8; ni++) {
        int c = ni * 8 + 2 * t4;
        Og[(qb + r0) * DEPTH + c]         = oacc[ni][0] * inv0;
        Og[(qb + r0) * DEPTH + c + 1]     = oacc[ni][1] * inv0;
        Og[(qb + r0 + 8) * DEPTH + c]     = oacc[ni][2] * inv1;
        Og[(qb + r0 + 8) * DEPTH + c + 1] = oacc[ni][3] * inv1;
    }
}

// ===========================================================================
// Kernel 3: output projection (UNCHANGED from R5).
// ===========================================================================
__global__ __launch_bounds__(256) void out_gemm(
    const float* __restrict__ Wo, const float* __restrict__ bo,
    float* __restrict__ out)
{
    extern __shared__ float sm[];
    float (*As)[GA_STRIDE] = (float (*)[GA_STRIDE])sm;
    float (*Bs)[GB_STRIDE] = (float (*)[GB_STRIDE])(sm + 2 * 128 * GA_STRIDE);

    const int nBase = blockIdx.x * 128;
    const int mBase = blockIdx.y * 128;

    const int tid  = threadIdx.x;
    const int warp = tid >> 5;
    const int lane = tid & 31;
    const int g    = lane >> 2;
    const int t4   = lane & 3;
    const int wRow = (warp >> 2) * 64;
    const int wCol = (warp & 3) * 32;

    const int aRow = tid >> 3;
    const int aC4  = (tid & 7) << 2;
    const int bR   = tid >> 5;
    const int bC4  = (tid & 31) << 2;

    float4 ra[4], rb[4];

    auto ldg_tiles = [&](int kb) {
        const int h = kb >> 6, e0 = (kb & 63) + aC4;
#pragma unroll
        for (int i = 0; i < 4; i++) {
            int m  = mBase + aRow + i * 32;
            int bb = m >> 11, s = m & 2047;
            ra[i] = *reinterpret_cast<const float4*>(
                &g_heads[(((size_t)(bb * NUM_HEADS + h) * SEQ) + s) * DEPTH + e0]);
        }
#pragma unroll
        for (int i = 0; i < 4; i++)
            rb[i] = *reinterpret_cast<const float4*>(
                &Wo[(size_t)(kb + bR + i * 8) * D_MODEL + nBase + bC4]);
    };
    auto sts_tiles = [&](int buf) {
#pragma unroll
        for (int i = 0; i < 4; i++)
            *reinterpret_cast<float4*>(&As[buf * 128 + aRow + i * 32][aC4]) = cvt4(ra[i]);
#pragma unroll
        for (int i = 0; i < 4; i++)
            *reinterpret_cast<float4*>(&Bs[buf * 32 + bR + i * 8][bC4]) = cvt4(rb[i]);
    };

    float acc[4][4][4];
#pragma unroll
    for (int i = 0; i < 4; i++)
#pragma unroll
        for (int j = 0; j < 4; j++)
#pragma unroll
            for (int r = 0; r < 4; r++) acc[i][j][r] = 0.f;

    ldg_tiles(0);
    sts_tiles(0);
    __syncthreads();

    const int NIT = D_MODEL / 32;
    for (int it = 0; it < NIT; ++it) {
        const int cur = it & 1, nxt = cur ^ 1;
        if (it + 1 < NIT) ldg_tiles((it + 1) * 32);

#pragma unroll
        for (int kk = 0; kk < 32; kk += 8) {
            uint32_t a[4][4], b[4][2];
#pragma unroll
            for (int mi = 0; mi < 4; mi++) {
                int r0 = cur * 128 + wRow + mi * 16 + g;
                a[mi][0] = __float_as_uint(As[r0][kk + t4]);
                a[mi][1] = __float_as_uint(As[r0 + 8][kk + t4]);
                a[mi][2] = __float_as_uint(As[r0][kk + t4 + 4]);
                a[mi][3] = __float_as_uint(As[r0 + 8][kk + t4 + 4]);
            }
#pragma unroll
            for (int ni = 0; ni < 4; ni++) {
                int c0 = wCol + ni * 8 + g;
                b[ni][0] = __float_as_uint(Bs[cur * 32 + kk + t4][c0]);
                b[ni][1] = __float_as_uint(Bs[cur * 32 + kk + t4 + 4][c0]);
            }
#pragma unroll
            for (int mi = 0; mi < 4; mi++)
#pragma unroll
                for (int ni = 0; ni < 4; ni++) mma8(acc[mi][ni], a[mi], b[ni]);
        }

        if (it + 1 < NIT) sts_tiles(nxt);
        __syncthreads();
    }

#pragma unroll
    for (int mi = 0; mi < 4; mi++) {
#pragma unroll
        for (int ni = 0; ni < 4; ni++) {
            int row = wRow + mi * 16 + g;
            int col = wCol + ni * 8 + 2 * t4;
#pragma unroll
            for (int r = 0; r < 4; r++) {
                int rr = row + ((r >= 2) ? 8 : 0);
                int cc = col + (r & 1);
                int m  = mBase + rr;
                int n  = nBase + cc;
                out[m * D_MODEL + n] = acc[mi][ni][r] + bo[n];
            }
        }
    }
}

// ===========================================================================
// Launch
// ===========================================================================
extern "C" void kernel_launch(void* const* d_in, const int* in_sizes, int n_in,
                              void* d_out, int out_size)
{
    (void)in_sizes; (void)n_in; (void)out_size;
    const float* x  = (const float*)d_in[0];
    const float* Wq = (const float*)d_in[1];
    const float* bq = (const float*)d_in[2];
    const float* Wk = (const float*)d_in[3];
    const float* bk = (const float*)d_in[4];
    const float* Wv = (const float*)d_in[5];
    const float* bv = (const float*)d_in[6];
    const float* Wo = (const float*)d_in[7];
    const float* bo = (const float*)d_in[8];
    float* out = (float*)d_out;

    cudaFuncSetAttribute(qkv_gemm, cudaFuncAttributeMaxDynamicSharedMemorySize,
                         GEMM_SMEM_BYTES);
    cudaFuncSetAttribute(out_gemm, cudaFuncAttributeMaxDynamicSharedMemorySize,
                         GEMM_SMEM_BYTES);
    cudaFuncSetAttribute(attn_kernel, cudaFuncAttributeMaxDynamicSharedMemorySize,
                         ATT_SMEM_BYTES);

    qkv_gemm<<<dim3(24, 64), 256, GEMM_SMEM_BYTES>>>(x, Wq, bq, Wk, bk, Wv, bv);
    attn_kernel<<<dim3(SEQ / QROWS, BATCH * NUM_HEADS), 256, ATT_SMEM_BYTES>>>();
    out_gemm<<<dim3(8, 64), 256, GEMM_SMEM_BYTES>>>(Wo, bo, out);
}